// round 2
// baseline (speedup 1.0000x reference)
#include <cuda_runtime.h>
#include <cuda_bf16.h>
#include <math.h>

// Problem constants (fixed by setup_inputs)
#define BB 512       // batch
#define TT 64        // text seq len
#define EE 50        // embedding dim
#define HH 32        // rnn hidden
#define NN 32768     // timeline sequences
#define TT2 32       // timeline seq len
#define FC_IN 305
#define HID 32

// ---------------- scratch (no allocations allowed) ----------------
__device__ float g_h2[(size_t)NN * 2 * HH];    // [N, 64] timeline biRNN final hidden
__device__ float g_hn[(size_t)BB * 2 * HH];    // [B, 64] text biRNN final hidden
__device__ float g_mean[(size_t)BB * 2 * HH];
__device__ float g_min [(size_t)BB * 2 * HH];
__device__ float g_max [(size_t)BB * 2 * HH];

// ---------------- bidirectional RNN kernel ----------------
// warp-per-(sequence, direction). lane i computes h[i].
// Weights per lane held in registers; x[e] and h[j] broadcast via shfl.
// 4 split accumulators to break the FFMA RAW chain; x prefetched one step ahead.
template <int T, bool TO_H2>
__global__ __launch_bounds__(256, 2)
void birnn_kernel(const float* __restrict__ x, int S,
                  const float* __restrict__ wif, const float* __restrict__ whf,
                  const float* __restrict__ bif, const float* __restrict__ bhf,
                  const float* __restrict__ wib, const float* __restrict__ whb,
                  const float* __restrict__ bib, const float* __restrict__ bhb)
{
    __shared__ float s_wi[2][HH * EE];   // 2 x 1600 floats
    __shared__ float s_wh[2][HH * HH];   // 2 x 1024 floats
    __shared__ float s_b [2][HH];

    const int tid = threadIdx.x;
    for (int k = tid; k < HH * EE; k += blockDim.x) { s_wi[0][k] = wif[k]; s_wi[1][k] = wib[k]; }
    for (int k = tid; k < HH * HH; k += blockDim.x) { s_wh[0][k] = whf[k]; s_wh[1][k] = whb[k]; }
    if (tid < HH)  { s_b[0][tid] = bif[tid] + bhf[tid]; }
    else if (tid < 2 * HH) { int j = tid - HH; s_b[1][j] = bib[j] + bhb[j]; }
    __syncthreads();

    const int warp = (int)((blockIdx.x * blockDim.x + tid) >> 5);
    const int lane = tid & 31;
    if (warp >= 2 * S) return;
    const int dir = warp & 1;        // 0 = forward, 1 = backward
    const int seq = warp >> 1;

    // per-lane weight rows -> registers
    float wi[EE], wh[HH];
#pragma unroll
    for (int e = 0; e < EE; e++) wi[e] = s_wi[dir][lane * EE + e];
#pragma unroll
    for (int j = 0; j < HH; j++) wh[j] = s_wh[dir][lane * HH + j];
    const float bias = s_b[dir][lane];

    float h = 0.f;
    const float* __restrict__ xp = x + (size_t)seq * T * EE;

    // prefetch t = 0
    const float* xt0 = xp + (size_t)(dir ? (T - 1) : 0) * EE;
    float x1 = xt0[lane];
    float x2 = (lane < EE - 32) ? xt0[32 + lane] : 0.f;

#pragma unroll 1
    for (int t = 0; t < T; t++) {
        // prefetch next timestep's x before the FMA chain
        float nx1 = 0.f, nx2 = 0.f;
        if (t + 1 < T) {
            const float* xtn = xp + (size_t)(dir ? (T - 2 - t) : (t + 1)) * EE;
            nx1 = xtn[lane];
            nx2 = (lane < EE - 32) ? xtn[32 + lane] : 0.f;
        }

        // 4 independent accumulator chains
        float a0 = bias, a1 = 0.f, a2 = 0.f, a3 = 0.f;
#pragma unroll
        for (int e = 0; e < 32; e += 4) {
            a0 = fmaf(__shfl_sync(0xffffffffu, x1, e + 0), wi[e + 0], a0);
            a1 = fmaf(__shfl_sync(0xffffffffu, x1, e + 1), wi[e + 1], a1);
            a2 = fmaf(__shfl_sync(0xffffffffu, x1, e + 2), wi[e + 2], a2);
            a3 = fmaf(__shfl_sync(0xffffffffu, x1, e + 3), wi[e + 3], a3);
        }
#pragma unroll
        for (int e = 0; e < 16; e += 4) {   // e covers 32..47
            a0 = fmaf(__shfl_sync(0xffffffffu, x2, e + 0), wi[32 + e + 0], a0);
            a1 = fmaf(__shfl_sync(0xffffffffu, x2, e + 1), wi[32 + e + 1], a1);
            a2 = fmaf(__shfl_sync(0xffffffffu, x2, e + 2), wi[32 + e + 2], a2);
            a3 = fmaf(__shfl_sync(0xffffffffu, x2, e + 3), wi[32 + e + 3], a3);
        }
        a0 = fmaf(__shfl_sync(0xffffffffu, x2, 16), wi[48], a0);   // e = 48
        a1 = fmaf(__shfl_sync(0xffffffffu, x2, 17), wi[49], a1);   // e = 49
#pragma unroll
        for (int j = 0; j < 32; j += 4) {
            a0 = fmaf(__shfl_sync(0xffffffffu, h, j + 0), wh[j + 0], a0);
            a1 = fmaf(__shfl_sync(0xffffffffu, h, j + 1), wh[j + 1], a1);
            a2 = fmaf(__shfl_sync(0xffffffffu, h, j + 2), wh[j + 2], a2);
            a3 = fmaf(__shfl_sync(0xffffffffu, h, j + 3), wh[j + 3], a3);
        }
        h = tanhf((a0 + a2) + (a1 + a3));

        x1 = nx1;
        x2 = nx2;
    }

    float* out = TO_H2 ? g_h2 : g_hn;
    out[(size_t)seq * (2 * HH) + dir * HH + lane] = h;
}

// ---------------- ragged segment mean/min/max ----------------
// one block per batch row b; 64 threads = one column each. Segments are contiguous.
__global__ void seg_kernel(const int* __restrict__ counts)
{
    const int b = blockIdx.x;
    const int c = threadIdx.x;   // 0..63
    size_t start = 0;
    for (int i = 0; i < b; i++) start += (size_t)counts[i];
    const int cnt = counts[b];

    float s = 0.f, mn = 2.f, mx = -2.f;   // h2 entries are tanh outputs in [-1,1]
    for (int r = 0; r < cnt; r++) {
        const float v = g_h2[(start + (size_t)r) * (2 * HH) + c];
        s += v;
        mn = fminf(mn, v);
        mx = fmaxf(mx, v);
    }
    g_mean[b * (2 * HH) + c] = s / (float)cnt;
    g_min [b * (2 * HH) + c] = mn;
    g_max [b * (2 * HH) + c] = mx;
}

// ---------------- final FC: tanh(fc1) -> sigmoid(fc2) ----------------
// warp per batch row; lane i computes fc1 output i, warp-reduce for fc2.
__global__ void fc_kernel(const float* __restrict__ normal,
                          const float* __restrict__ fc1w, const float* __restrict__ fc1b,
                          const float* __restrict__ fc2w, const float* __restrict__ fc2b,
                          float* __restrict__ out)
{
    const int warp = (int)((blockIdx.x * blockDim.x + threadIdx.x) >> 5);
    const int lane = threadIdx.x & 31;
    if (warp >= BB) return;
    const int b = warp;

    float acc = fc1b[lane];
    const float* __restrict__ w = fc1w + (size_t)lane * FC_IN;
    // concat order: h_n(64) | normal(49) | mean(64) | min(64) | max(64)
#pragma unroll 8
    for (int k = 0; k < 64; k++) acc = fmaf(g_hn[b * 64 + k], w[k], acc);
#pragma unroll 7
    for (int k = 0; k < 49; k++) acc = fmaf(normal[b * 49 + k], w[64 + k], acc);
#pragma unroll 8
    for (int k = 0; k < 64; k++) acc = fmaf(g_mean[b * 64 + k], w[113 + k], acc);
#pragma unroll 8
    for (int k = 0; k < 64; k++) acc = fmaf(g_min[b * 64 + k], w[177 + k], acc);
#pragma unroll 8
    for (int k = 0; k < 64; k++) acc = fmaf(g_max[b * 64 + k], w[241 + k], acc);

    float tv = tanhf(acc) * fc2w[lane];
#pragma unroll
    for (int o = 16; o > 0; o >>= 1) tv += __shfl_xor_sync(0xffffffffu, tv, o);
    if (lane == 0) out[b] = 1.f / (1.f + expf(-(tv + fc2b[0])));
}

// ---------------- launch ----------------
extern "C" void kernel_launch(void* const* d_in, const int* in_sizes, int n_in,
                              void* d_out, int out_size)
{
    const float* normal   = (const float*)d_in[0];
    const float* text     = (const float*)d_in[1];
    const float* timeline = (const float*)d_in[2];

    // Two plausible metadata orders; disambiguate by in_sizes[3]:
    //   A (setup_inputs dict order): slot 3 = timeline_elements (512), weights at 4..
    //   B (reference signature order): weights at 3.., timeline_elements last (slot 23)
    const int* telem;
    int base;
    if (in_sizes[3] == BB) { telem = (const int*)d_in[3];  base = 4; }
    else                   { telem = (const int*)d_in[23]; base = 3; }

    const float* r1[8];
    const float* r2[8];
    for (int k = 0; k < 8; k++) r1[k] = (const float*)d_in[base + k];
    for (int k = 0; k < 8; k++) r2[k] = (const float*)d_in[base + 8 + k];
    const float* fc1w = (const float*)d_in[base + 16];
    const float* fc1b = (const float*)d_in[base + 17];
    const float* fc2w = (const float*)d_in[base + 18];
    const float* fc2b = (const float*)d_in[base + 19];
    float* out = (float*)d_out;

    const int THREADS = 256;

    // timeline biRNN: 2*N warps
    {
        int warps = 2 * NN;
        int blocks = (warps * 32 + THREADS - 1) / THREADS;
        birnn_kernel<TT2, true><<<blocks, THREADS>>>(timeline, NN,
            r2[0], r2[1], r2[2], r2[3], r2[4], r2[5], r2[6], r2[7]);
    }
    // text biRNN: 2*B warps
    {
        int warps = 2 * BB;
        int blocks = (warps * 32 + THREADS - 1) / THREADS;
        birnn_kernel<TT, false><<<blocks, THREADS>>>(text, BB,
            r1[0], r1[1], r1[2], r1[3], r1[4], r1[5], r1[6], r1[7]);
    }
    // segment stats
    seg_kernel<<<BB, 2 * HH>>>(telem);
    // final FC
    {
        int warps = BB;
        int blocks = (warps * 32 + THREADS - 1) / THREADS;
        fc_kernel<<<blocks, THREADS>>>(normal, fc1w, fc1b, fc2w, fc2b, out);
    }
    (void)n_in; (void)in_sizes; (void)out_size;
}

// round 6
// speedup vs baseline: 2.5241x; 2.5241x over previous
#include <cuda_runtime.h>
#include <cuda_bf16.h>
#include <math.h>
#include <stdint.h>

// Problem constants (fixed by setup_inputs)
#define BB 512       // batch
#define TT 64        // text seq len
#define EE 50        // embedding dim
#define HH 32        // rnn hidden
#define NN 32768     // timeline sequences
#define TT2 32       // timeline seq len
#define FC_IN 305

// ---------------- scratch (no allocations allowed) ----------------
__device__ float g_h2[(size_t)NN * 64];    // [N, 64] timeline biRNN final hidden
__device__ float g_hn[(size_t)BB * 64];    // [B, 64] text biRNN final hidden

// ==================== helpers (plain sm_100-safe PTX: sm_80+ features only) ====================
__device__ __forceinline__ uint32_t smem_u32(const void* p) {
    uint32_t a;
    asm("{ .reg .u64 t; cvta.to.shared.u64 t, %1; cvt.u32.u64 %0, t; }" : "=r"(a) : "l"(p));
    return a;
}
__device__ __forceinline__ uint32_t f2tf(float f) {
    uint32_t r; asm("cvt.rna.tf32.f32 %0, %1;" : "=r"(r) : "f"(f)); return r;
}
__device__ __forceinline__ float lds_f(uint32_t a) {
    float v; asm volatile("ld.shared.f32 %0, [%1];" : "=f"(v) : "r"(a)); return v;
}
__device__ __forceinline__ void sts_f(uint32_t a, float v) {
    asm volatile("st.shared.f32 [%0], %1;" :: "r"(a), "f"(v));
}
__device__ __forceinline__ void sts_v2(uint32_t a, float x, float y) {
    asm volatile("st.shared.v2.f32 [%0], {%1, %2};" :: "r"(a), "f"(x), "f"(y));
}
__device__ __forceinline__ void cp_async8(uint32_t saddr, const void* gaddr) {
    asm volatile("cp.async.ca.shared.global [%0], [%1], 8;" :: "r"(saddr), "l"(gaddr));
}
#define CP_COMMIT() asm volatile("cp.async.commit_group;" ::: "memory")
#define CP_WAIT0()  asm volatile("cp.async.wait_group 0;" ::: "memory")

// D += A*B : m16n8k8 tf32 (A row-major, B col-major), fp32 accum
__device__ __forceinline__ void mma8(float c[4], const uint32_t a[4], const uint32_t b[2]) {
    asm volatile("mma.sync.aligned.m16n8k8.row.col.f32.tf32.tf32.f32 "
        "{%0,%1,%2,%3}, {%4,%5,%6,%7}, {%8,%9}, {%0,%1,%2,%3};"
        : "+f"(c[0]), "+f"(c[1]), "+f"(c[2]), "+f"(c[3])
        : "r"(a[0]), "r"(a[1]), "r"(a[2]), "r"(a[3]), "r"(b[0]), "r"(b[1]));
}

__device__ __forceinline__ float ftanh(float x) {
    float cx = fminf(fmaxf(x, -15.f), 15.f);
    float e = __expf(2.f * cx);
    return (e - 1.f) * __frcp_rn(e + 1.f);
}

// ==================== per-warp SMEM layout (timeline branch) ====================
// xbuf: 16 rows x 60 floats (50 data + pad, cols 50..59 zeroed), double-buffered
// hbuf: 16 rows x 36 floats (32 data + pad)
#define XBUF_BYTES  (16 * 60 * 4)     // 3840
#define WARP_SMEM   (2 * XBUF_BYTES + 16 * 36 * 4)   // 3840*2 + 2304 = 9984
// CTA: 4 warps -> 39936 bytes (< 48KB static limit)

// ==================== fused RNN kernel ====================
// blocks 0..1023:    timeline biRNN via mma.sync tf32 (dir = b&1, 64 seqs per CTA)
// blocks 1024..1279: text biRNN via shuffle path (4 warps/block)
__global__ __launch_bounds__(128)
void fused_rnn(const float* __restrict__ tlx, const float* __restrict__ txx,
               const float* __restrict__ r2wif, const float* __restrict__ r2whf,
               const float* __restrict__ r2bif, const float* __restrict__ r2bhf,
               const float* __restrict__ r2wib, const float* __restrict__ r2whb,
               const float* __restrict__ r2bib, const float* __restrict__ r2bhb,
               const float* __restrict__ r1wif, const float* __restrict__ r1whf,
               const float* __restrict__ r1bif, const float* __restrict__ r1bhf,
               const float* __restrict__ r1wib, const float* __restrict__ r1whb,
               const float* __restrict__ r1bib, const float* __restrict__ r1bhb)
{
    __shared__ __align__(16) unsigned char s_raw[4 * WARP_SMEM];
    const int tid  = threadIdx.x;
    const int wid  = tid >> 5;
    const int lane = tid & 31;

    if (blockIdx.x < 1024) {
        // ---------------- timeline tensor-core path ----------------
        const int dir  = (int)(blockIdx.x & 1);
        const int tile = (int)(blockIdx.x >> 1);
        const int n0w  = tile * 64 + wid * 16;      // warp's first sequence

        const float* wih = dir ? r2wib : r2wif;
        const float* whh = dir ? r2whb : r2whf;
        const float* bi  = dir ? r2bib : r2bif;
        const float* bh  = dir ? r2bhb : r2bhf;

        const int g  = lane >> 2;    // 0..7
        const int t4 = lane & 3;     // 0..3

        const uint32_t wb  = smem_u32(s_raw) + (uint32_t)wid * WARP_SMEM;
        const uint32_t xb0 = wb;
        const uint32_t xb1 = wb + XBUF_BYTES;
        const uint32_t hb  = wb + 2 * XBUF_BYTES;

        // zero pad columns 50..59 of both x buffers (k-tile 6 reads cols 48..55)
        if (lane < 16) {
#pragma unroll
            for (int k = 0; k < 10; k++) {
                sts_f(xb0 + (uint32_t)(lane * 60 + 50 + k) * 4u, 0.f);
                sts_f(xb1 + (uint32_t)(lane * 60 + 50 + k) * 4u, 0.f);
            }
        }

        // ---- weight B-fragments (col-major B[k][n] = W[n][k]), tf32 in registers ----
        uint32_t wbh[4][4][2];   // h part: K=32
#pragma unroll
        for (int kt = 0; kt < 4; kt++)
#pragma unroll
            for (int nt = 0; nt < 4; nt++) {
                int row = nt * 8 + g;
                wbh[kt][nt][0] = f2tf(whh[row * 32 + kt * 8 + t4]);
                wbh[kt][nt][1] = f2tf(whh[row * 32 + kt * 8 + t4 + 4]);
            }
        uint32_t wbx[7][4][2];   // x part: K=56 (50 padded)
#pragma unroll
        for (int kx = 0; kx < 7; kx++)
#pragma unroll
            for (int nt = 0; nt < 4; nt++) {
                int row = nt * 8 + g;
                int c0 = kx * 8 + t4, c1 = c0 + 4;
                wbx[kx][nt][0] = (c0 < EE) ? f2tf(wih[row * EE + c0]) : 0u;
                wbx[kx][nt][1] = (c1 < EE) ? f2tf(wih[row * EE + c1]) : 0u;
            }
        float bb[4][2];
#pragma unroll
        for (int nt = 0; nt < 4; nt++) {
            int col = nt * 8 + t4 * 2;
            bb[nt][0] = bi[col] + bh[col];
            bb[nt][1] = bi[col + 1] + bh[col + 1];
        }

        // ---- x staging plan: row = lane&15, half = lane>>4 ----
        const int xrow = lane & 15;
        const int half = lane >> 4;              // 0: cols 0..25 (13 x 8B); 1: cols 26..49 (12 x 8B)
        const float* grow = tlx + (size_t)(n0w + xrow) * (TT2 * EE) + half * 26;
        const uint32_t soff = (uint32_t)(xrow * 60 + half * 26) * 4u;

        // stage t = 0 into buf0
        {
            int te0 = dir ? (TT2 - 1) : 0;
            const float* gp = grow + te0 * EE;
#pragma unroll
            for (int j = 0; j < 13; j++)
                if (half == 0 || j < 12)
                    cp_async8(xb0 + soff + 8u * j, gp + 2 * j);
            CP_COMMIT();
            CP_WAIT0();
            __syncwarp();
        }

        uint32_t ha[4][4];
#pragma unroll
        for (int kt = 0; kt < 4; kt++)
#pragma unroll
            for (int i = 0; i < 4; i++) ha[kt][i] = 0u;

        float acc[4][4];

#pragma unroll 1
        for (int t = 0; t < TT2; t++) {
            // prefetch x(t+1) into alternate buffer
            if (t + 1 < TT2) {
                int te = dir ? (TT2 - 2 - t) : (t + 1);
                uint32_t dst = ((t + 1) & 1) ? xb1 : xb0;
                const float* gp = grow + te * EE;
#pragma unroll
                for (int j = 0; j < 13; j++)
                    if (half == 0 || j < 12)
                        cp_async8(dst + soff + 8u * j, gp + 2 * j);
                CP_COMMIT();
            }

            // acc = bias
#pragma unroll
            for (int nt = 0; nt < 4; nt++) {
                acc[nt][0] = bb[nt][0]; acc[nt][1] = bb[nt][1];
                acc[nt][2] = bb[nt][0]; acc[nt][3] = bb[nt][1];
            }
            // h contribution
#pragma unroll
            for (int kt = 0; kt < 4; kt++)
#pragma unroll
                for (int nt = 0; nt < 4; nt++)
                    mma8(acc[nt], ha[kt], wbh[kt][nt]);
            // x contribution
            const uint32_t cur = (t & 1) ? xb1 : xb0;
#pragma unroll
            for (int kx = 0; kx < 7; kx++) {
                uint32_t xa[4];
                uint32_t ba = cur + (uint32_t)(g * 240 + kx * 32 + t4 * 4);
                xa[0] = f2tf(lds_f(ba));
                xa[1] = f2tf(lds_f(ba + 1920u));
                xa[2] = f2tf(lds_f(ba + 16u));
                xa[3] = f2tf(lds_f(ba + 1936u));
#pragma unroll
                for (int nt = 0; nt < 4; nt++)
                    mma8(acc[nt], xa, wbx[kx][nt]);
            }
            // tanh (in place)
#pragma unroll
            for (int nt = 0; nt < 4; nt++)
#pragma unroll
                for (int i = 0; i < 4; i++)
                    acc[nt][i] = ftanh(acc[nt][i]);

            if (t == TT2 - 1) {
#pragma unroll
                for (int nt = 0; nt < 4; nt++) {
                    int col = dir * 32 + nt * 8 + t4 * 2;
                    float2 v01 = make_float2(acc[nt][0], acc[nt][1]);
                    float2 v23 = make_float2(acc[nt][2], acc[nt][3]);
                    *(float2*)(g_h2 + (size_t)(n0w + g) * 64 + col)     = v01;
                    *(float2*)(g_h2 + (size_t)(n0w + g + 8) * 64 + col) = v23;
                }
            } else {
                // write h to smem (C layout), then reload as A fragments
#pragma unroll
                for (int nt = 0; nt < 4; nt++) {
                    uint32_t a0 = hb + (uint32_t)(g * 36 + nt * 8 + t4 * 2) * 4u;
                    sts_v2(a0,           acc[nt][0], acc[nt][1]);
                    sts_v2(a0 + 1152u,   acc[nt][2], acc[nt][3]);   // row g+8
                }
                CP_WAIT0();      // x prefetch done
                __syncwarp();    // h visible warp-wide
#pragma unroll
                for (int kt = 0; kt < 4; kt++) {
                    uint32_t ba = hb + (uint32_t)(g * 144 + kt * 32 + t4 * 4);
                    ha[kt][0] = f2tf(lds_f(ba));
                    ha[kt][1] = f2tf(lds_f(ba + 1152u));
                    ha[kt][2] = f2tf(lds_f(ba + 16u));
                    ha[kt][3] = f2tf(lds_f(ba + 1168u));
                }
            }
        }
        return;
    }

    // ---------------- text shuffle path (blocks 1024..1279, 4 warps each) ----------------
    {
        float* s_wi = (float*)s_raw;                        // [2][HH*EE]
        float* s_wh = s_wi + 2 * HH * EE;                   // [2][HH*HH]
        float* s_b  = s_wh + 2 * HH * HH;                   // [2][HH]

        for (int k = tid; k < HH * EE; k += 128) { s_wi[k] = r1wif[k]; s_wi[HH * EE + k] = r1wib[k]; }
        for (int k = tid; k < HH * HH; k += 128) { s_wh[k] = r1whf[k]; s_wh[HH * HH + k] = r1whb[k]; }
        if (tid < HH) s_b[tid] = r1bif[tid] + r1bhf[tid];
        else if (tid < 2 * HH) { int j = tid - HH; s_b[HH + j] = r1bib[j] + r1bhb[j]; }
        __syncthreads();

        const int wglob = ((int)blockIdx.x - 1024) * 4 + wid;   // 0..1023
        const int dir = wglob & 1;
        const int seq = wglob >> 1;

        float wi[EE], wh[HH];
#pragma unroll
        for (int e = 0; e < EE; e++) wi[e] = s_wi[dir * HH * EE + lane * EE + e];
#pragma unroll
        for (int j = 0; j < HH; j++) wh[j] = s_wh[dir * HH * HH + lane * HH + j];
        const float biasv = s_b[dir * HH + lane];

        float h = 0.f;
        const float* xp = txx + (size_t)seq * TT * EE;

        const float* xt0 = xp + (size_t)(dir ? (TT - 1) : 0) * EE;
        float x1 = xt0[lane];
        float x2 = (lane < EE - 32) ? xt0[32 + lane] : 0.f;

#pragma unroll 1
        for (int t = 0; t < TT; t++) {
            float nx1 = 0.f, nx2 = 0.f;
            if (t + 1 < TT) {
                const float* xtn = xp + (size_t)(dir ? (TT - 2 - t) : (t + 1)) * EE;
                nx1 = xtn[lane];
                nx2 = (lane < EE - 32) ? xtn[32 + lane] : 0.f;
            }
            float a0 = biasv, a1 = 0.f, a2 = 0.f, a3 = 0.f;
#pragma unroll
            for (int e = 0; e < 32; e += 4) {
                a0 = fmaf(__shfl_sync(0xffffffffu, x1, e + 0), wi[e + 0], a0);
                a1 = fmaf(__shfl_sync(0xffffffffu, x1, e + 1), wi[e + 1], a1);
                a2 = fmaf(__shfl_sync(0xffffffffu, x1, e + 2), wi[e + 2], a2);
                a3 = fmaf(__shfl_sync(0xffffffffu, x1, e + 3), wi[e + 3], a3);
            }
#pragma unroll
            for (int e = 0; e < 16; e += 4) {
                a0 = fmaf(__shfl_sync(0xffffffffu, x2, e + 0), wi[32 + e + 0], a0);
                a1 = fmaf(__shfl_sync(0xffffffffu, x2, e + 1), wi[32 + e + 1], a1);
                a2 = fmaf(__shfl_sync(0xffffffffu, x2, e + 2), wi[32 + e + 2], a2);
                a3 = fmaf(__shfl_sync(0xffffffffu, x2, e + 3), wi[32 + e + 3], a3);
            }
            a0 = fmaf(__shfl_sync(0xffffffffu, x2, 16), wi[48], a0);
            a1 = fmaf(__shfl_sync(0xffffffffu, x2, 17), wi[49], a1);
#pragma unroll
            for (int j = 0; j < 32; j += 4) {
                a0 = fmaf(__shfl_sync(0xffffffffu, h, j + 0), wh[j + 0], a0);
                a1 = fmaf(__shfl_sync(0xffffffffu, h, j + 1), wh[j + 1], a1);
                a2 = fmaf(__shfl_sync(0xffffffffu, h, j + 2), wh[j + 2], a2);
                a3 = fmaf(__shfl_sync(0xffffffffu, h, j + 3), wh[j + 3], a3);
            }
            h = tanhf((a0 + a2) + (a1 + a3));
            x1 = nx1; x2 = nx2;
        }
        g_hn[(size_t)seq * 64 + dir * 32 + lane] = h;
    }
}

// ==================== fused segment stats + FC ====================
__global__ void segfc_kernel(const int* __restrict__ counts,
                             const float* __restrict__ normal,
                             const float* __restrict__ fc1w, const float* __restrict__ fc1b,
                             const float* __restrict__ fc2w, const float* __restrict__ fc2b,
                             float* __restrict__ out)
{
    __shared__ float feat[FC_IN];
    __shared__ int wsum[2];
    const int b = blockIdx.x;
    const int c = threadIdx.x;   // 0..63

    int part = 0;
    for (int i = c; i < b; i += 64) part += counts[i];
#pragma unroll
    for (int o = 16; o > 0; o >>= 1) part += __shfl_xor_sync(0xffffffffu, part, o);
    if ((c & 31) == 0) wsum[c >> 5] = part;
    __syncthreads();
    const size_t start = (size_t)(wsum[0] + wsum[1]);
    const int cnt = counts[b];

    float s = 0.f, mn = 2.f, mx = -2.f;
    const float* p = g_h2 + start * 64 + c;
    for (int r = 0; r < cnt; r++) {
        float v = p[(size_t)r * 64];
        s += v; mn = fminf(mn, v); mx = fmaxf(mx, v);
    }
    feat[c] = g_hn[(size_t)b * 64 + c];
    if (c < 49) feat[64 + c] = normal[(size_t)b * 49 + c];
    feat[113 + c] = s / (float)cnt;
    feat[177 + c] = mn;
    feat[241 + c] = mx;
    __syncthreads();

    if (c < 32) {
        float a0 = fc1b[c], a1 = 0.f, a2 = 0.f, a3 = 0.f;
        const float* w = fc1w + (size_t)c * FC_IN;
#pragma unroll 4
        for (int k = 0; k < 304; k += 4) {
            a0 = fmaf(feat[k + 0], w[k + 0], a0);
            a1 = fmaf(feat[k + 1], w[k + 1], a1);
            a2 = fmaf(feat[k + 2], w[k + 2], a2);
            a3 = fmaf(feat[k + 3], w[k + 3], a3);
        }
        a0 = fmaf(feat[304], w[304], a0);
        float tv = tanhf((a0 + a2) + (a1 + a3)) * fc2w[c];
#pragma unroll
        for (int o = 16; o > 0; o >>= 1) tv += __shfl_xor_sync(0xffffffffu, tv, o);
        if (c == 0) out[b] = 1.f / (1.f + expf(-(tv + fc2b[0])));
    }
}

// ==================== launch ====================
extern "C" void kernel_launch(void* const* d_in, const int* in_sizes, int n_in,
                              void* d_out, int out_size)
{
    const float* normal   = (const float*)d_in[0];
    const float* text     = (const float*)d_in[1];
    const float* timeline = (const float*)d_in[2];

    const int* telem;
    int base;
    if (in_sizes[3] == BB) { telem = (const int*)d_in[3];  base = 4; }
    else                   { telem = (const int*)d_in[23]; base = 3; }

    const float* r1[8];
    const float* r2[8];
    for (int k = 0; k < 8; k++) r1[k] = (const float*)d_in[base + k];
    for (int k = 0; k < 8; k++) r2[k] = (const float*)d_in[base + 8 + k];
    const float* fc1w = (const float*)d_in[base + 16];
    const float* fc1b = (const float*)d_in[base + 17];
    const float* fc2w = (const float*)d_in[base + 18];
    const float* fc2b = (const float*)d_in[base + 19];
    float* out = (float*)d_out;

    fused_rnn<<<1280, 128>>>(timeline, text,
        r2[0], r2[1], r2[2], r2[3], r2[4], r2[5], r2[6], r2[7],
        r1[0], r1[1], r1[2], r1[3], r1[4], r1[5], r1[6], r1[7]);

    segfc_kernel<<<BB, 64>>>(telem, normal, fc1w, fc1b, fc2w, fc2b, out);

    (void)n_in; (void)in_sizes; (void)out_size;
}